// round 14
// baseline (speedup 1.0000x reference)
#include <cuda_runtime.h>
#include <cuda_bf16.h>
#include <math.h>
#include <stdint.h>

#define LQ 2048
#define DMODEL 3072
#define NHEAD 24
#define HDIM 128
#define MLPD 12288
#define N1 21504   // 3*D + MLP
#define DM 15360   // D + MLP
#define TD3 9216   // 3*D

// ---------------- scratch (device globals; no allocation allowed) ----------------
__device__ float g_mod[3 * DMODEL];          // [shift | scale | gate]
__device__ float g_q[(size_t)NHEAD * LQ * HDIM];
__device__ float g_k[(size_t)NHEAD * LQ * HDIM];
__device__ float g_v[(size_t)NHEAD * LQ * HDIM];

// split-bf16 operands (hi/lo): A matrices [M][K], B matrices [N][K]
__device__ __align__(128) __nv_bfloat16 g_a1h[(size_t)LQ * DMODEL];
__device__ __align__(128) __nv_bfloat16 g_a1l[(size_t)LQ * DMODEL];
__device__ __align__(128) __nv_bfloat16 g_b1h[(size_t)N1 * DMODEL];
__device__ __align__(128) __nv_bfloat16 g_b1l[(size_t)N1 * DMODEL];
__device__ __align__(128) __nv_bfloat16 g_a2h[(size_t)LQ * DM];
__device__ __align__(128) __nv_bfloat16 g_a2l[(size_t)LQ * DM];
__device__ __align__(128) __nv_bfloat16 g_b2h[(size_t)DMODEL * DM];
__device__ __align__(128) __nv_bfloat16 g_b2l[(size_t)DMODEL * DM];

// ---------------- PTX helpers ----------------
#define CP16(saddr, gptr) \
    asm volatile("cp.async.cg.shared.global [%0], [%1], 16;\n" \
                 :: "r"(saddr), "l"(gptr))
#define CP_COMMIT() asm volatile("cp.async.commit_group;\n")
#define CP_WAIT(n)  asm volatile("cp.async.wait_group %0;\n" :: "n"(n))

__device__ __forceinline__ void mma_bf16(float* c, const uint32_t* a,
                                         uint32_t b0, uint32_t b1) {
    asm volatile(
        "mma.sync.aligned.m16n8k16.row.col.f32.bf16.bf16.f32 "
        "{%0,%1,%2,%3}, {%4,%5,%6,%7}, {%8,%9}, {%0,%1,%2,%3};"
        : "+f"(c[0]), "+f"(c[1]), "+f"(c[2]), "+f"(c[3])
        : "r"(a[0]), "r"(a[1]), "r"(a[2]), "r"(a[3]), "r"(b0), "r"(b1));
}

// packed fp32x2 (FFMA2)
#define FMA2(c, a, b) \
    asm("fma.rn.f32x2 %0, %1, %2, %0;" : "+l"(c) : "l"(a), "l"(b))
#define MUL2(c, a) \
    asm("mul.rn.f32x2 %0, %0, %1;" : "+l"(c) : "l"(a))

__device__ __forceinline__ unsigned long long pack2(float lo, float hi) {
    unsigned long long r;
    asm("mov.b64 %0, {%1,%2};" : "=l"(r)
        : "r"(__float_as_uint(lo)), "r"(__float_as_uint(hi)));
    return r;
}
__device__ __forceinline__ float pairsum(unsigned long long v) {
    return __uint_as_float((unsigned)v) + __uint_as_float((unsigned)(v >> 32));
}

__device__ __forceinline__ void split_store(__nv_bfloat16* dh, __nv_bfloat16* dl,
                                            size_t idx, float v) {
    __nv_bfloat16 h = __float2bfloat16(v);
    dh[idx] = h;
    dl[idx] = __float2bfloat16(v - __bfloat162float(h));
}

__device__ __forceinline__ void split_store2(__nv_bfloat16* dh, __nv_bfloat16* dl,
                                             size_t idx, float v0, float v1) {
    __nv_bfloat16 h0 = __float2bfloat16(v0);
    __nv_bfloat16 h1 = __float2bfloat16(v1);
    __nv_bfloat162 hh; hh.x = h0; hh.y = h1;
    *(__nv_bfloat162*)&dh[idx] = hh;
    __nv_bfloat162 ll;
    ll.x = __float2bfloat16(v0 - __bfloat162float(h0));
    ll.y = __float2bfloat16(v1 - __bfloat162float(h1));
    *(__nv_bfloat162*)&dl[idx] = ll;
}

// HW tanh (MUFU.TANH)
__device__ __forceinline__ float gelu_tanh(float v) {
    float arg = 0.7978845608028654f * (v + 0.044715f * v * v * v);
    float t;
    asm("tanh.approx.f32 %0, %1;" : "=f"(t) : "f"(arg));
    return 0.5f * v * (1.f + t);
}

// ---------------- K0: mod = silu(vec) @ mod_w + mod_b (split-K + atomics) ----
__global__ void k_zero() { g_mod[blockIdx.x * 256 + threadIdx.x] = 0.f; }

__global__ void k_mod(const float* __restrict__ vec,
                      const float* __restrict__ mod_w,
                      const float* __restrict__ mod_b) {
    __shared__ float sv[384];
    int k0 = blockIdx.y * 384;
    for (int i = threadIdx.x; i < 384; i += 256) {
        float v = vec[k0 + i];
        sv[i] = v / (1.0f + expf(-v));
    }
    __syncthreads();
    int col = blockIdx.x * 256 + threadIdx.x;
    float acc = (blockIdx.y == 0) ? mod_b[col] : 0.f;
    for (int i = 0; i < 384; ++i)
        acc = fmaf(sv[i], mod_w[(size_t)(k0 + i) * (3 * DMODEL) + col], acc);
    atomicAdd(&g_mod[col], acc);
}

__device__ __forceinline__ float block_sum_256(float v, float* red8) {
    #pragma unroll
    for (int o = 16; o > 0; o >>= 1) v += __shfl_xor_sync(0xffffffffu, v, o);
    if ((threadIdx.x & 31) == 0) red8[threadIdx.x >> 5] = v;
    __syncthreads();
    float t = 0.f;
    #pragma unroll
    for (int i = 0; i < 8; ++i) t += red8[i];
    __syncthreads();
    return t;
}

// ---------------- K1: x_mod -> bf16 hi/lo (float4 loads, paired stores) --------
__global__ void k_xmod(const float* __restrict__ x) {
    __shared__ float red8[8];
    int t = blockIdx.x;
    const float* xr = x + (size_t)t * DMODEL;
    float s = 0.f;
    for (int i = threadIdx.x * 4; i < DMODEL; i += 1024) {
        float4 v = *(const float4*)&xr[i];
        s += (v.x + v.y) + (v.z + v.w);
    }
    float mu = block_sum_256(s, red8) * (1.0f / DMODEL);
    float vs = 0.f;
    for (int i = threadIdx.x * 4; i < DMODEL; i += 1024) {
        float4 v = *(const float4*)&xr[i];
        float d0 = v.x - mu, d1 = v.y - mu, d2 = v.z - mu, d3 = v.w - mu;
        vs += d0 * d0 + d1 * d1 + d2 * d2 + d3 * d3;
    }
    float var = block_sum_256(vs, red8) * (1.0f / DMODEL);
    float rstd = rsqrtf(var + 1e-6f);
    for (int i = threadIdx.x * 4; i < DMODEL; i += 1024) {
        float4 v = *(const float4*)&xr[i];
        float4 sh = *(const float4*)&g_mod[i];
        float4 sc = *(const float4*)&g_mod[DMODEL + i];
        float o0 = sh.x + (1.0f + sc.x) * ((v.x - mu) * rstd);
        float o1 = sh.y + (1.0f + sc.y) * ((v.y - mu) * rstd);
        float o2 = sh.z + (1.0f + sc.z) * ((v.z - mu) * rstd);
        float o3 = sh.w + (1.0f + sc.w) * ((v.w - mu) * rstd);
        size_t base = (size_t)t * DMODEL + i;
        split_store2(g_a1h, g_a1l, base, o0, o1);
        split_store2(g_a1h, g_a1l, base + 2, o2, o3);
    }
}

// ---------------- transpose + split (v3b): 64x64 tile, MLP=4, scalar STS ------
// src[R][C] fp32 -> dst[C][R] bf16 hi/lo. 256 threads, 16 floats/thread.
__global__ void k_cvt_t(const float* __restrict__ src,
                        __nv_bfloat16* __restrict__ dh,
                        __nv_bfloat16* __restrict__ dl, int R, int C) {
    __shared__ float tile[64][65];
    int c0 = blockIdx.x * 64, r0 = blockIdx.y * 64;
    int t = threadIdx.x;
    // load: 4 independent LDG.128 per thread; scalar smem stores (65-pitch)
    {
        int r = t >> 2, c16 = (t & 3) * 16;
        const float* s0 = &src[(size_t)(r0 + r) * C + c0 + c16];
        float4 v0 = *(const float4*)(s0 + 0);
        float4 v1 = *(const float4*)(s0 + 4);
        float4 v2 = *(const float4*)(s0 + 8);
        float4 v3 = *(const float4*)(s0 + 12);
        float* tr = &tile[r][c16];
        tr[0] = v0.x;  tr[1] = v0.y;  tr[2] = v0.z;  tr[3] = v0.w;
        tr[4] = v1.x;  tr[5] = v1.y;  tr[6] = v1.z;  tr[7] = v1.w;
        tr[8] = v2.x;  tr[9] = v2.y;  tr[10] = v2.z; tr[11] = v2.w;
        tr[12] = v3.x; tr[13] = v3.y; tr[14] = v3.z; tr[15] = v3.w;
    }
    __syncthreads();
    // store: 16 rows of one column -> 4 packed uint2 per array
    {
        int c = t >> 2, r16 = (t & 3) * 16;
        size_t base = (size_t)(c0 + c) * R + r0 + r16;
        #pragma unroll
        for (int q = 0; q < 4; q++) {
            float f0 = tile[r16 + 4 * q + 0][c];
            float f1 = tile[r16 + 4 * q + 1][c];
            float f2 = tile[r16 + 4 * q + 2][c];
            float f3 = tile[r16 + 4 * q + 3][c];
            __nv_bfloat16 h0 = __float2bfloat16(f0);
            __nv_bfloat16 h1 = __float2bfloat16(f1);
            __nv_bfloat16 h2 = __float2bfloat16(f2);
            __nv_bfloat16 h3 = __float2bfloat16(f3);
            uint2 hp;
            hp.x = ((uint32_t)*(uint16_t*)&h0) | (((uint32_t)*(uint16_t*)&h1) << 16);
            hp.y = ((uint32_t)*(uint16_t*)&h2) | (((uint32_t)*(uint16_t*)&h3) << 16);
            *(uint2*)&dh[base + 4 * q] = hp;
            __nv_bfloat16 l0 = __float2bfloat16(f0 - __bfloat162float(h0));
            __nv_bfloat16 l1 = __float2bfloat16(f1 - __bfloat162float(h1));
            __nv_bfloat16 l2 = __float2bfloat16(f2 - __bfloat162float(h2));
            __nv_bfloat16 l3 = __float2bfloat16(f3 - __bfloat162float(h3));
            uint2 lp;
            lp.x = ((uint32_t)*(uint16_t*)&l0) | (((uint32_t)*(uint16_t*)&l1) << 16);
            lp.y = ((uint32_t)*(uint16_t*)&l2) | (((uint32_t)*(uint16_t*)&l3) << 16);
            *(uint2*)&dl[base + 4 * q] = lp;
        }
    }
}

// ---------------- split-bf16 HMMA GEMM (round-4 proven mainloop) ----------------
#define ROWW 40
#define SLAB_W 2560
#define STAGE_B 40960
#define GEMM_SMEM (2 * STAGE_B)

__device__ __forceinline__ void ld_stage_b(
    const __nv_bfloat16* Ah, const __nv_bfloat16* Al,
    const __nv_bfloat16* Bh, const __nv_bfloat16* Bl,
    int K, int m0, int n0, int k0, uint32_t sm, int tid) {
    int row = tid >> 1;
    int cb = (tid & 1) * 32;
    uint32_t so = row * (ROWW * 2) + cb;
    const char* ga = (const char*)(Ah + (size_t)(m0 + row) * K + k0) + cb;
    CP16(sm + so, ga); CP16(sm + so + 16, ga + 16);
    const char* gal = (const char*)(Al + (size_t)(m0 + row) * K + k0) + cb;
    CP16(sm + 10240 + so, gal); CP16(sm + 10240 + so + 16, gal + 16);
    const char* gb = (const char*)(Bh + (size_t)(n0 + row) * K + k0) + cb;
    CP16(sm + 20480 + so, gb); CP16(sm + 20480 + so + 16, gb + 16);
    const char* gbl = (const char*)(Bl + (size_t)(n0 + row) * K + k0) + cb;
    CP16(sm + 30720 + so, gbl); CP16(sm + 30720 + so + 16, gbl + 16);
}

template <int EPI>
__global__ __launch_bounds__(256, 2) void k_gemm_bf(
    const __nv_bfloat16* __restrict__ Ah, const __nv_bfloat16* __restrict__ Al,
    const __nv_bfloat16* __restrict__ Bh, const __nv_bfloat16* __restrict__ Bl,
    int K, const float* __restrict__ bias,
    const float* __restrict__ x, float* __restrict__ out) {
    extern __shared__ __align__(16) char smc[];
    uint32_t sbase;
    asm("{ .reg .u64 t; cvta.to.shared.u64 t, %1; cvt.u32.u64 %0, t; }"
        : "=r"(sbase) : "l"(smc));

    int tid = threadIdx.x;
    int m0 = blockIdx.x * 128;
    int n0 = blockIdx.y * 128;
    int lane = tid & 31, w = tid >> 5;
    int g = lane >> 2, t4 = lane & 3;
    int wm = w & 3, wn = w >> 2;

    float c[2][8][4];
    #pragma unroll
    for (int mi = 0; mi < 2; mi++)
        #pragma unroll
        for (int ni = 0; ni < 8; ni++)
            #pragma unroll
            for (int cc = 0; cc < 4; cc++) c[mi][ni][cc] = 0.f;

    int nst = K / 32;
    ld_stage_b(Ah, Al, Bh, Bl, K, m0, n0, 0, sbase, tid);
    CP_COMMIT();

    for (int kt = 0; kt < nst; ++kt) {
        if (kt + 1 < nst) {
            ld_stage_b(Ah, Al, Bh, Bl, K, m0, n0, (kt + 1) * 32,
                       sbase + ((kt + 1) & 1) * STAGE_B, tid);
            CP_COMMIT();
            CP_WAIT(1);
        } else {
            CP_WAIT(0);
        }
        __syncthreads();

        const uint32_t* st = (const uint32_t*)(smc + (kt & 1) * STAGE_B);
        const uint32_t* sal = st + SLAB_W;
        const uint32_t* sbh = st + 2 * SLAB_W;
        const uint32_t* sbl = st + 3 * SLAB_W;

        #pragma unroll
        for (int ks = 0; ks < 2; ks++) {
            int kw = ks * 8;
            uint32_t ah[2][4], al[2][4];
            #pragma unroll
            for (int mi = 0; mi < 2; mi++) {
                int r = wm * 32 + mi * 16;
                int bi = (r + g) * 20 + t4 + kw;
                ah[mi][0] = st[bi];        ah[mi][1] = st[bi + 160];
                ah[mi][2] = st[bi + 4];    ah[mi][3] = st[bi + 164];
                al[mi][0] = sal[bi];       al[mi][1] = sal[bi + 160];
                al[mi][2] = sal[bi + 4];   al[mi][3] = sal[bi + 164];
            }
            #pragma unroll
            for (int p = 0; p < 4; p++) {
                int n = wn * 64 + p * 16;
                int bj = (n + g) * 20 + t4 + kw;
                uint32_t bh0 = sbh[bj], bh1 = sbh[bj + 4];
                uint32_t bl0 = sbl[bj], bl1 = sbl[bj + 4];
                mma_bf16(c[0][2 * p], ah[0], bh0, bh1);
                mma_bf16(c[1][2 * p], ah[1], bh0, bh1);
                mma_bf16(c[0][2 * p], al[0], bh0, bh1);
                mma_bf16(c[1][2 * p], al[1], bh0, bh1);
                mma_bf16(c[0][2 * p], ah[0], bl0, bl1);
                mma_bf16(c[1][2 * p], ah[1], bl0, bl1);
                int bj2 = (n + 8 + g) * 20 + t4 + kw;
                uint32_t ch0 = sbh[bj2], ch1 = sbh[bj2 + 4];
                uint32_t cl0 = sbl[bj2], cl1 = sbl[bj2 + 4];
                mma_bf16(c[0][2 * p + 1], ah[0], ch0, ch1);
                mma_bf16(c[1][2 * p + 1], ah[1], ch0, ch1);
                mma_bf16(c[0][2 * p + 1], al[0], ch0, ch1);
                mma_bf16(c[1][2 * p + 1], al[1], ch0, ch1);
                mma_bf16(c[0][2 * p + 1], ah[0], cl0, cl1);
                mma_bf16(c[1][2 * p + 1], ah[1], cl0, cl1);
            }
        }
        __syncthreads();
    }

    // ---- epilogue: paired stores (cc pairs are adjacent n, same m) ----
    if (EPI == 0) {
        bool is_qkv = n0 < TD3;
        float* qkvdst = nullptr;
        if (is_qkv) {
            int which = n0 / DMODEL;
            int head = (n0 % DMODEL) / HDIM;
            float* base = (which == 0) ? g_q : (which == 1) ? g_k : g_v;
            qkvdst = base + (size_t)head * LQ * HDIM;
        }
        #pragma unroll
        for (int mi = 0; mi < 2; mi++)
            #pragma unroll
            for (int ni = 0; ni < 8; ni++)
                #pragma unroll
                for (int p2 = 0; p2 < 2; p2++) {
                    int m = m0 + wm * 32 + mi * 16 + g + p2 * 8;
                    int dcol = wn * 64 + ni * 8 + 2 * t4;
                    int n = n0 + dcol;
                    float2 bb = *(const float2*)&bias[n];
                    float v0 = c[mi][ni][2 * p2] + bb.x;
                    float v1 = c[mi][ni][2 * p2 + 1] + bb.y;
                    if (is_qkv) {
                        float2 o; o.x = v0; o.y = v1;
                        *(float2*)&qkvdst[(size_t)m * HDIM + dcol] = o;
                    } else {
                        split_store2(g_a2h, g_a2l, (size_t)m * DM + (n - 6144),
                                     gelu_tanh(v0), gelu_tanh(v1));
                    }
                }
    } else {
        #pragma unroll
        for (int mi = 0; mi < 2; mi++)
            #pragma unroll
            for (int ni = 0; ni < 8; ni++)
                #pragma unroll
                for (int p2 = 0; p2 < 2; p2++) {
                    int m = m0 + wm * 32 + mi * 16 + g + p2 * 8;
                    int n = n0 + wn * 64 + ni * 8 + 2 * t4;
                    float2 bb = *(const float2*)&bias[n];
                    float v0 = c[mi][ni][2 * p2] + bb.x;
                    float v1 = c[mi][ni][2 * p2 + 1] + bb.y;
                    float2 xx = *(const float2*)&x[(size_t)m * DMODEL + n];
                    float2 gg = *(const float2*)&g_mod[2 * DMODEL + n];
                    float2 o;
                    o.x = xx.x + gg.x * v0;
                    o.y = xx.y + gg.y * v1;
                    *(float2*)&out[(size_t)m * DMODEL + n] = o;
                }
    }
}

// ---------------- K3: rms_norm + rope, q and k in one block ----------------
__global__ void k_rmsrope(const float* __restrict__ pe,
                          const float* __restrict__ q_scale,
                          const float* __restrict__ k_scale) {
    int t = blockIdx.x, h = blockIdx.y;
    int tid = threadIdx.x;
    int half = tid >> 7;        // 0 = q, 1 = k
    int d = tid & 127;
    float* buf = (half == 0 ? g_q : g_k) + ((size_t)h * LQ + t) * HDIM;
    const float* sc = (half == 0) ? q_scale : k_scale;
    __shared__ float spe[256];
    __shared__ float red[2][4];
    __shared__ float sv[2][HDIM];
    spe[tid] = pe[(size_t)t * 256 + tid];
    float v = buf[d];
    float ss = v * v;
    #pragma unroll
    for (int o = 16; o > 0; o >>= 1) ss += __shfl_xor_sync(0xffffffffu, ss, o);
    if ((d & 31) == 0) red[half][(d >> 5)] = ss;
    __syncthreads();
    float tot = red[half][0] + red[half][1] + red[half][2] + red[half][3];
    float n = rsqrtf(tot * (1.0f / HDIM) + 1e-6f);
    sv[half][d] = v * n * sc[d];
    __syncthreads();
    int j = d >> 1, r = d & 1;
    buf[d] = spe[j * 4 + r * 2] * sv[half][2 * j] +
             spe[j * 4 + r * 2 + 1] * sv[half][2 * j + 1];
}

// ---------------- K4: flash attention with packed f32x2 FMAs ----------------
#define QP 134
#define VP 66
#define PP 68
#define ATTN_SMEM_FLOATS (64 * QP + 64 * QP + 128 * VP + 64 * PP)
__global__ __launch_bounds__(256, 1) void k_attn() {
    extern __shared__ __align__(16) float smf[];
    float* sQ = smf;
    float* sK = sQ + 64 * QP;
    float* sV = sK + 64 * QP;
    float* sP = sV + 128 * VP;
    int head = blockIdx.y;
    int qt0 = blockIdx.x * 64;
    int tid = threadIdx.x;
    const float* Qg = g_q + (size_t)head * LQ * HDIM;
    const float* Kg = g_k + (size_t)head * LQ * HDIM;
    const float* Vg = g_v + (size_t)head * LQ * HDIM;

    {
        int c = tid >> 2, d0 = (tid & 3) * 32;
        const float* src = Qg + (size_t)(qt0 + c) * HDIM + d0;
        #pragma unroll
        for (int u = 0; u < 8; ++u) {
            float4 v = *(const float4*)(src + 4 * u);
            *(float2*)&sQ[c * QP + d0 + 4 * u] = make_float2(v.x, v.y);
            *(float2*)&sQ[c * QP + d0 + 4 * u + 2] = make_float2(v.z, v.w);
        }
    }

    int rq = (tid >> 4) * 4;
    int cl = tid & 15;

    float m_i[4], l_i[4];
    unsigned long long o2[4][8];
    #pragma unroll
    for (int i = 0; i < 4; i++) {
        m_i[i] = -INFINITY; l_i[i] = 0.f;
        #pragma unroll
        for (int u = 0; u < 8; u++) o2[i][u] = 0ull;
    }
    const float scale = 0.08838834764831845f;

    for (int kt0 = 0; kt0 < LQ; kt0 += 64) {
        __syncthreads();
        {
            int c = tid >> 2, d0 = (tid & 3) * 32;
            const float* srck = Kg + (size_t)(kt0 + c) * HDIM + d0;
            const float* srcv = Vg + (size_t)(kt0 + c) * HDIM + d0;
            #pragma unroll
            for (int u = 0; u < 8; ++u) {
                float4 kv = *(const float4*)(srck + 4 * u);
                *(float2*)&sK[c * QP + d0 + 4 * u] = make_float2(kv.x, kv.y);
                *(float2*)&sK[c * QP + d0 + 4 * u + 2] = make_float2(kv.z, kv.w);
                float4 vv = *(const float4*)(srcv + 4 * u);
                sV[(d0 + 4 * u + 0) * VP + c] = vv.x;
                sV[(d0 + 4 * u + 1) * VP + c] = vv.y;
                sV[(d0 + 4 * u + 2) * VP + c] = vv.z;
                sV[(d0 + 4 * u + 3) * VP + c] = vv.w;
            }
        }
        __syncthreads();

        unsigned long long s2[4][4];
        #pragma unroll
        for (int i = 0; i < 4; i++)
            #pragma unroll
            for (int u = 0; u < 4; u++) s2[i][u] = 0ull;
        #pragma unroll 8
        for (int k2 = 0; k2 < 64; k2++) {
            unsigned long long a0 = *(const unsigned long long*)&sQ[(rq + 0) * QP + 2 * k2];
            unsigned long long a1 = *(const unsigned long long*)&sQ[(rq + 1) * QP + 2 * k2];
            unsigned long long a2 = *(const unsigned long long*)&sQ[(rq + 2) * QP + 2 * k2];
            unsigned long long a3 = *(const unsigned long long*)&sQ[(rq + 3) * QP + 2 * k2];
            #pragma unroll
            for (int u = 0; u < 4; u++) {
                unsigned long long b =
                    *(const unsigned long long*)&sK[(cl + 16 * u) * QP + 2 * k2];
                FMA2(s2[0][u], a0, b);
                FMA2(s2[1][u], a1, b);
                FMA2(s2[2][u], a2, b);
                FMA2(s2[3][u], a3, b);
            }
        }

        #pragma unroll
        for (int i = 0; i < 4; i++) {
            float s0 = pairsum(s2[i][0]) * scale;
            float s1 = pairsum(s2[i][1]) * scale;
            float s2v = pairsum(s2[i][2]) * scale;
            float s3 = pairsum(s2[i][3]) * scale;
            float tm = fmaxf(fmaxf(s0, s1), fmaxf(s2v, s3));
            #pragma unroll
            for (int off = 8; off > 0; off >>= 1)
                tm = fmaxf(tm, __shfl_xor_sync(0xffffffffu, tm, off));
            float newm = fmaxf(m_i[i], tm);
            float corr = __expf(m_i[i] - newm);
            float p0 = __expf(s0 - newm), p1 = __expf(s1 - newm);
            float p2 = __expf(s2v - newm), p3 = __expf(s3 - newm);
            float ls = p0 + p1 + p2 + p3;
            #pragma unroll
            for (int off = 8; off > 0; off >>= 1)
                ls += __shfl_xor_sync(0xffffffffu, ls, off);
            l_i[i] = l_i[i] * corr + ls;
            m_i[i] = newm;
            unsigned long long corr2 = pack2(corr, corr);
            #pragma unroll
            for (int u = 0; u < 8; u++) MUL2(o2[i][u], corr2);
            sP[(rq + i) * PP + cl + 0]  = p0;
            sP[(rq + i) * PP + cl + 16] = p1;
            sP[(rq + i) * PP + cl + 32] = p2;
            sP[(rq + i) * PP + cl + 48] = p3;
        }
        __syncthreads();

        #pragma unroll 4
        for (int c2 = 0; c2 < 32; c2++) {
            unsigned long long a0 = *(const unsigned long long*)&sP[(rq + 0) * PP + 2 * c2];
            unsigned long long a1 = *(const unsigned long long*)&sP[(rq + 1) * PP + 2 * c2];
            unsigned long long a2 = *(const unsigned long long*)&sP[(rq + 2) * PP + 2 * c2];
            unsigned long long a3 = *(const unsigned long long*)&sP[(rq + 3) * PP + 2 * c2];
            #pragma unroll
            for (int u = 0; u < 8; u++) {
                unsigned long long b =
                    *(const unsigned long long*)&sV[(cl + 16 * u) * VP + 2 * c2];
                FMA2(o2[0][u], a0, b);
                FMA2(o2[1][u], a1, b);
                FMA2(o2[2][u], a2, b);
                FMA2(o2[3][u], a3, b);
            }
        }
    }

    #pragma unroll
    for (int i = 0; i < 4; i++) {
        float inv = 1.f / l_i[i];
        int t = qt0 + rq + i;
        size_t rowb = (size_t)t * DM + head * HDIM;
        #pragma unroll
        for (int u = 0; u < 8; u++) {
            float val = pairsum(o2[i][u]) * inv;
            split_store(g_a2h, g_a2l, rowb + cl + 16 * u, val);
        }
    }
}

// ---------------- launch ----------------
extern "C" void kernel_launch(void* const* d_in, const int* in_sizes, int n_in,
                              void* d_out, int out_size) {
    (void)in_sizes; (void)n_in; (void)out_size;
    const float* x       = (const float*)d_in[1];
    const float* vec     = (const float*)d_in[2];
    const float* pe      = (const float*)d_in[3];
    const float* mod_w   = (const float*)d_in[4];
    const float* mod_b   = (const float*)d_in[5];
    const float* w1      = (const float*)d_in[6];
    const float* b1      = (const float*)d_in[7];
    const float* w2      = (const float*)d_in[8];
    const float* b2      = (const float*)d_in[9];
    const float* q_scale = (const float*)d_in[10];
    const float* k_scale = (const float*)d_in[11];
    float* out = (float*)d_out;

    static int attr_done = 0;
    if (!attr_done) {
        cudaFuncSetAttribute(k_attn, cudaFuncAttributeMaxDynamicSharedMemorySize,
                             ATTN_SMEM_FLOATS * (int)sizeof(float));
        cudaFuncSetAttribute(k_gemm_bf<0>,
                             cudaFuncAttributeMaxDynamicSharedMemorySize, GEMM_SMEM);
        cudaFuncSetAttribute(k_gemm_bf<1>,
                             cudaFuncAttributeMaxDynamicSharedMemorySize, GEMM_SMEM);
        attr_done = 1;
    }
    static __nv_bfloat16 *a1h, *a1l, *b1h, *b1l, *a2h, *a2l, *b2h, *b2l;
    if (!a1h) {
        cudaGetSymbolAddress((void**)&a1h, g_a1h);
        cudaGetSymbolAddress((void**)&a1l, g_a1l);
        cudaGetSymbolAddress((void**)&b1h, g_b1h);
        cudaGetSymbolAddress((void**)&b1l, g_b1l);
        cudaGetSymbolAddress((void**)&a2h, g_a2h);
        cudaGetSymbolAddress((void**)&a2l, g_a2l);
        cudaGetSymbolAddress((void**)&b2h, g_b2h);
        cudaGetSymbolAddress((void**)&b2l, g_b2l);
    }

    k_zero<<<(3 * DMODEL) / 256, 256>>>();
    k_mod<<<dim3((3 * DMODEL) / 256, 8), 256>>>(vec, mod_w, mod_b);
    k_xmod<<<LQ, 256>>>(x);
    k_cvt_t<<<dim3(N1 / 64, DMODEL / 64), 256>>>(w1, b1h, b1l, DMODEL, N1);
    k_gemm_bf<0><<<dim3(LQ / 128, N1 / 128), 256, GEMM_SMEM>>>(
        a1h, a1l, b1h, b1l, DMODEL, b1, nullptr, nullptr);
    k_rmsrope<<<dim3(LQ, NHEAD), 256>>>(pe, q_scale, k_scale);
    k_attn<<<dim3(LQ / 64, NHEAD), 256, ATTN_SMEM_FLOATS * sizeof(float)>>>();
    k_cvt_t<<<dim3(DMODEL / 64, DM / 64), 256>>>(w2, b2h, b2l, DM, DMODEL);
    k_gemm_bf<1><<<dim3(LQ / 128, DMODEL / 128), 256, GEMM_SMEM>>>(
        a2h, a2l, b2h, b2l, DM, b2, x, out);
}

// round 15
// speedup vs baseline: 1.0168x; 1.0168x over previous
#include <cuda_runtime.h>
#include <cuda_bf16.h>
#include <math.h>
#include <stdint.h>

#define LQ 2048
#define DMODEL 3072
#define NHEAD 24
#define HDIM 128
#define MLPD 12288
#define N1 21504   // 3*D + MLP
#define DM 15360   // D + MLP
#define TD3 9216   // 3*D

// ---------------- scratch (device globals; no allocation allowed) ----------------
__device__ float g_mod[3 * DMODEL];          // [shift | scale | gate]
__device__ float g_q[(size_t)NHEAD * LQ * HDIM];
__device__ float g_k[(size_t)NHEAD * LQ * HDIM];
__device__ float g_v[(size_t)NHEAD * LQ * HDIM];

// split-bf16 operands (hi/lo): A matrices [M][K], B matrices [N][K]
__device__ __align__(128) __nv_bfloat16 g_a1h[(size_t)LQ * DMODEL];
__device__ __align__(128) __nv_bfloat16 g_a1l[(size_t)LQ * DMODEL];
__device__ __align__(128) __nv_bfloat16 g_b1h[(size_t)N1 * DMODEL];
__device__ __align__(128) __nv_bfloat16 g_b1l[(size_t)N1 * DMODEL];
__device__ __align__(128) __nv_bfloat16 g_a2h[(size_t)LQ * DM];
__device__ __align__(128) __nv_bfloat16 g_a2l[(size_t)LQ * DM];
__device__ __align__(128) __nv_bfloat16 g_b2h[(size_t)DMODEL * DM];
__device__ __align__(128) __nv_bfloat16 g_b2l[(size_t)DMODEL * DM];

// ---------------- PTX helpers ----------------
#define CP16(saddr, gptr) \
    asm volatile("cp.async.cg.shared.global [%0], [%1], 16;\n" \
                 :: "r"(saddr), "l"(gptr))
#define CP_COMMIT() asm volatile("cp.async.commit_group;\n")
#define CP_WAIT(n)  asm volatile("cp.async.wait_group %0;\n" :: "n"(n))

__device__ __forceinline__ void mma_bf16(float* c, const uint32_t* a,
                                         uint32_t b0, uint32_t b1) {
    asm volatile(
        "mma.sync.aligned.m16n8k16.row.col.f32.bf16.bf16.f32 "
        "{%0,%1,%2,%3}, {%4,%5,%6,%7}, {%8,%9}, {%0,%1,%2,%3};"
        : "+f"(c[0]), "+f"(c[1]), "+f"(c[2]), "+f"(c[3])
        : "r"(a[0]), "r"(a[1]), "r"(a[2]), "r"(a[3]), "r"(b0), "r"(b1));
}

// packed fp32x2 (FFMA2)
#define FMA2(c, a, b) \
    asm("fma.rn.f32x2 %0, %1, %2, %0;" : "+l"(c) : "l"(a), "l"(b))
#define MUL2(c, a) \
    asm("mul.rn.f32x2 %0, %0, %1;" : "+l"(c) : "l"(a))

__device__ __forceinline__ unsigned long long pack2(float lo, float hi) {
    unsigned long long r;
    asm("mov.b64 %0, {%1,%2};" : "=l"(r)
        : "r"(__float_as_uint(lo)), "r"(__float_as_uint(hi)));
    return r;
}
__device__ __forceinline__ float pairsum(unsigned long long v) {
    return __uint_as_float((unsigned)v) + __uint_as_float((unsigned)(v >> 32));
}

__device__ __forceinline__ void split_store(__nv_bfloat16* dh, __nv_bfloat16* dl,
                                            size_t idx, float v) {
    __nv_bfloat16 h = __float2bfloat16(v);
    dh[idx] = h;
    dl[idx] = __float2bfloat16(v - __bfloat162float(h));
}

__device__ __forceinline__ void split_store2(__nv_bfloat16* dh, __nv_bfloat16* dl,
                                             size_t idx, float v0, float v1) {
    __nv_bfloat16 h0 = __float2bfloat16(v0);
    __nv_bfloat16 h1 = __float2bfloat16(v1);
    __nv_bfloat162 hh; hh.x = h0; hh.y = h1;
    *(__nv_bfloat162*)&dh[idx] = hh;
    __nv_bfloat162 ll;
    ll.x = __float2bfloat16(v0 - __bfloat162float(h0));
    ll.y = __float2bfloat16(v1 - __bfloat162float(h1));
    *(__nv_bfloat162*)&dl[idx] = ll;
}

// HW tanh (MUFU.TANH)
__device__ __forceinline__ float gelu_tanh(float v) {
    float arg = 0.7978845608028654f * (v + 0.044715f * v * v * v);
    float t;
    asm("tanh.approx.f32 %0, %1;" : "=f"(t) : "f"(arg));
    return 0.5f * v * (1.f + t);
}

// ---------------- K0: mod = silu(vec) @ mod_w + mod_b (split-K + atomics) ----
__global__ void k_zero() { g_mod[blockIdx.x * 256 + threadIdx.x] = 0.f; }

__global__ void k_mod(const float* __restrict__ vec,
                      const float* __restrict__ mod_w,
                      const float* __restrict__ mod_b) {
    __shared__ float sv[384];
    int k0 = blockIdx.y * 384;
    for (int i = threadIdx.x; i < 384; i += 256) {
        float v = vec[k0 + i];
        sv[i] = v / (1.0f + expf(-v));
    }
    __syncthreads();
    int col = blockIdx.x * 256 + threadIdx.x;
    float acc = (blockIdx.y == 0) ? mod_b[col] : 0.f;
    for (int i = 0; i < 384; ++i)
        acc = fmaf(sv[i], mod_w[(size_t)(k0 + i) * (3 * DMODEL) + col], acc);
    atomicAdd(&g_mod[col], acc);
}

__device__ __forceinline__ float block_sum_256(float v, float* red8) {
    #pragma unroll
    for (int o = 16; o > 0; o >>= 1) v += __shfl_xor_sync(0xffffffffu, v, o);
    if ((threadIdx.x & 31) == 0) red8[threadIdx.x >> 5] = v;
    __syncthreads();
    float t = 0.f;
    #pragma unroll
    for (int i = 0; i < 8; ++i) t += red8[i];
    __syncthreads();
    return t;
}

// ---------------- K1: x_mod -> bf16 hi/lo (float4 loads, paired stores) --------
__global__ void k_xmod(const float* __restrict__ x) {
    __shared__ float red8[8];
    int t = blockIdx.x;
    const float* xr = x + (size_t)t * DMODEL;
    float s = 0.f;
    for (int i = threadIdx.x * 4; i < DMODEL; i += 1024) {
        float4 v = *(const float4*)&xr[i];
        s += (v.x + v.y) + (v.z + v.w);
    }
    float mu = block_sum_256(s, red8) * (1.0f / DMODEL);
    float vs = 0.f;
    for (int i = threadIdx.x * 4; i < DMODEL; i += 1024) {
        float4 v = *(const float4*)&xr[i];
        float d0 = v.x - mu, d1 = v.y - mu, d2 = v.z - mu, d3 = v.w - mu;
        vs += d0 * d0 + d1 * d1 + d2 * d2 + d3 * d3;
    }
    float var = block_sum_256(vs, red8) * (1.0f / DMODEL);
    float rstd = rsqrtf(var + 1e-6f);
    for (int i = threadIdx.x * 4; i < DMODEL; i += 1024) {
        float4 v = *(const float4*)&xr[i];
        float4 sh = *(const float4*)&g_mod[i];
        float4 sc = *(const float4*)&g_mod[DMODEL + i];
        float o0 = sh.x + (1.0f + sc.x) * ((v.x - mu) * rstd);
        float o1 = sh.y + (1.0f + sc.y) * ((v.y - mu) * rstd);
        float o2 = sh.z + (1.0f + sc.z) * ((v.z - mu) * rstd);
        float o3 = sh.w + (1.0f + sc.w) * ((v.w - mu) * rstd);
        size_t base = (size_t)t * DMODEL + i;
        split_store2(g_a1h, g_a1l, base, o0, o1);
        split_store2(g_a1h, g_a1l, base + 2, o2, o3);
    }
}

// ---------------- transpose + split (v4): dual 32x32 tiles, MLP=2 ----------
// src[R][C] fp32 -> dst[C][R] bf16 hi/lo. Two column-tiles per block; v2's
// proven conflict-free 32x33 pattern, both global loads front-batched.
__global__ void k_cvt_t(const float* __restrict__ src,
                        __nv_bfloat16* __restrict__ dh,
                        __nv_bfloat16* __restrict__ dl, int R, int C) {
    __shared__ float tile[2][32][33];
    int c0 = blockIdx.x * 64, r0 = blockIdx.y * 32;
    int t = threadIdx.x;
    {
        int r = t >> 3, c4 = (t & 7) * 4;
        const float* s0 = &src[(size_t)(r0 + r) * C + c0 + c4];
        float4 v0 = *(const float4*)(s0);
        float4 v1 = *(const float4*)(s0 + 32);
        tile[0][r][c4 + 0] = v0.x; tile[0][r][c4 + 1] = v0.y;
        tile[0][r][c4 + 2] = v0.z; tile[0][r][c4 + 3] = v0.w;
        tile[1][r][c4 + 0] = v1.x; tile[1][r][c4 + 1] = v1.y;
        tile[1][r][c4 + 2] = v1.z; tile[1][r][c4 + 3] = v1.w;
    }
    __syncthreads();
    #pragma unroll
    for (int q = 0; q < 2; q++) {
        int c = t >> 3, r4 = (t & 7) * 4;
        float f0 = tile[q][r4 + 0][c];
        float f1 = tile[q][r4 + 1][c];
        float f2 = tile[q][r4 + 2][c];
        float f3 = tile[q][r4 + 3][c];
        __nv_bfloat16 h0 = __float2bfloat16(f0);
        __nv_bfloat16 h1 = __float2bfloat16(f1);
        __nv_bfloat16 h2 = __float2bfloat16(f2);
        __nv_bfloat16 h3 = __float2bfloat16(f3);
        size_t idx = (size_t)(c0 + q * 32 + c) * R + r0 + r4;
        uint2 hp;
        hp.x = ((uint32_t)*(uint16_t*)&h0) | (((uint32_t)*(uint16_t*)&h1) << 16);
        hp.y = ((uint32_t)*(uint16_t*)&h2) | (((uint32_t)*(uint16_t*)&h3) << 16);
        *(uint2*)&dh[idx] = hp;
        __nv_bfloat16 l0 = __float2bfloat16(f0 - __bfloat162float(h0));
        __nv_bfloat16 l1 = __float2bfloat16(f1 - __bfloat162float(h1));
        __nv_bfloat16 l2 = __float2bfloat16(f2 - __bfloat162float(h2));
        __nv_bfloat16 l3 = __float2bfloat16(f3 - __bfloat162float(h3));
        uint2 lp;
        lp.x = ((uint32_t)*(uint16_t*)&l0) | (((uint32_t)*(uint16_t*)&l1) << 16);
        lp.y = ((uint32_t)*(uint16_t*)&l2) | (((uint32_t)*(uint16_t*)&l3) << 16);
        *(uint2*)&dl[idx] = lp;
    }
}

// ---------------- split-bf16 HMMA GEMM (round-4 proven mainloop) ----------------
#define ROWW 40
#define SLAB_W 2560
#define STAGE_B 40960
#define GEMM_SMEM (2 * STAGE_B)

__device__ __forceinline__ void ld_stage_b(
    const __nv_bfloat16* Ah, const __nv_bfloat16* Al,
    const __nv_bfloat16* Bh, const __nv_bfloat16* Bl,
    int K, int m0, int n0, int k0, uint32_t sm, int tid) {
    int row = tid >> 1;
    int cb = (tid & 1) * 32;
    uint32_t so = row * (ROWW * 2) + cb;
    const char* ga = (const char*)(Ah + (size_t)(m0 + row) * K + k0) + cb;
    CP16(sm + so, ga); CP16(sm + so + 16, ga + 16);
    const char* gal = (const char*)(Al + (size_t)(m0 + row) * K + k0) + cb;
    CP16(sm + 10240 + so, gal); CP16(sm + 10240 + so + 16, gal + 16);
    const char* gb = (const char*)(Bh + (size_t)(n0 + row) * K + k0) + cb;
    CP16(sm + 20480 + so, gb); CP16(sm + 20480 + so + 16, gb + 16);
    const char* gbl = (const char*)(Bl + (size_t)(n0 + row) * K + k0) + cb;
    CP16(sm + 30720 + so, gbl); CP16(sm + 30720 + so + 16, gbl + 16);
}

template <int EPI>
__global__ __launch_bounds__(256, 2) void k_gemm_bf(
    const __nv_bfloat16* __restrict__ Ah, const __nv_bfloat16* __restrict__ Al,
    const __nv_bfloat16* __restrict__ Bh, const __nv_bfloat16* __restrict__ Bl,
    int K, const float* __restrict__ bias,
    const float* __restrict__ x, float* __restrict__ out) {
    extern __shared__ __align__(16) char smc[];
    uint32_t sbase;
    asm("{ .reg .u64 t; cvta.to.shared.u64 t, %1; cvt.u32.u64 %0, t; }"
        : "=r"(sbase) : "l"(smc));

    int tid = threadIdx.x;
    int m0 = blockIdx.x * 128;
    int n0 = blockIdx.y * 128;
    int lane = tid & 31, w = tid >> 5;
    int g = lane >> 2, t4 = lane & 3;
    int wm = w & 3, wn = w >> 2;

    float c[2][8][4];
    #pragma unroll
    for (int mi = 0; mi < 2; mi++)
        #pragma unroll
        for (int ni = 0; ni < 8; ni++)
            #pragma unroll
            for (int cc = 0; cc < 4; cc++) c[mi][ni][cc] = 0.f;

    int nst = K / 32;
    ld_stage_b(Ah, Al, Bh, Bl, K, m0, n0, 0, sbase, tid);
    CP_COMMIT();

    for (int kt = 0; kt < nst; ++kt) {
        if (kt + 1 < nst) {
            ld_stage_b(Ah, Al, Bh, Bl, K, m0, n0, (kt + 1) * 32,
                       sbase + ((kt + 1) & 1) * STAGE_B, tid);
            CP_COMMIT();
            CP_WAIT(1);
        } else {
            CP_WAIT(0);
        }
        __syncthreads();

        const uint32_t* st = (const uint32_t*)(smc + (kt & 1) * STAGE_B);
        const uint32_t* sal = st + SLAB_W;
        const uint32_t* sbh = st + 2 * SLAB_W;
        const uint32_t* sbl = st + 3 * SLAB_W;

        #pragma unroll
        for (int ks = 0; ks < 2; ks++) {
            int kw = ks * 8;
            uint32_t ah[2][4], al[2][4];
            #pragma unroll
            for (int mi = 0; mi < 2; mi++) {
                int r = wm * 32 + mi * 16;
                int bi = (r + g) * 20 + t4 + kw;
                ah[mi][0] = st[bi];        ah[mi][1] = st[bi + 160];
                ah[mi][2] = st[bi + 4];    ah[mi][3] = st[bi + 164];
                al[mi][0] = sal[bi];       al[mi][1] = sal[bi + 160];
                al[mi][2] = sal[bi + 4];   al[mi][3] = sal[bi + 164];
            }
            #pragma unroll
            for (int p = 0; p < 4; p++) {
                int n = wn * 64 + p * 16;
                int bj = (n + g) * 20 + t4 + kw;
                uint32_t bh0 = sbh[bj], bh1 = sbh[bj + 4];
                uint32_t bl0 = sbl[bj], bl1 = sbl[bj + 4];
                mma_bf16(c[0][2 * p], ah[0], bh0, bh1);
                mma_bf16(c[1][2 * p], ah[1], bh0, bh1);
                mma_bf16(c[0][2 * p], al[0], bh0, bh1);
                mma_bf16(c[1][2 * p], al[1], bh0, bh1);
                mma_bf16(c[0][2 * p], ah[0], bl0, bl1);
                mma_bf16(c[1][2 * p], ah[1], bl0, bl1);
                int bj2 = (n + 8 + g) * 20 + t4 + kw;
                uint32_t ch0 = sbh[bj2], ch1 = sbh[bj2 + 4];
                uint32_t cl0 = sbl[bj2], cl1 = sbl[bj2 + 4];
                mma_bf16(c[0][2 * p + 1], ah[0], ch0, ch1);
                mma_bf16(c[1][2 * p + 1], ah[1], ch0, ch1);
                mma_bf16(c[0][2 * p + 1], al[0], ch0, ch1);
                mma_bf16(c[1][2 * p + 1], al[1], ch0, ch1);
                mma_bf16(c[0][2 * p + 1], ah[0], cl0, cl1);
                mma_bf16(c[1][2 * p + 1], ah[1], cl0, cl1);
            }
        }
        __syncthreads();
    }

    // ---- epilogue: paired stores (cc pairs are adjacent n, same m) ----
    if (EPI == 0) {
        bool is_qkv = n0 < TD3;
        float* qkvdst = nullptr;
        if (is_qkv) {
            int which = n0 / DMODEL;
            int head = (n0 % DMODEL) / HDIM;
            float* base = (which == 0) ? g_q : (which == 1) ? g_k : g_v;
            qkvdst = base + (size_t)head * LQ * HDIM;
        }
        #pragma unroll
        for (int mi = 0; mi < 2; mi++)
            #pragma unroll
            for (int ni = 0; ni < 8; ni++)
                #pragma unroll
                for (int p2 = 0; p2 < 2; p2++) {
                    int m = m0 + wm * 32 + mi * 16 + g + p2 * 8;
                    int dcol = wn * 64 + ni * 8 + 2 * t4;
                    int n = n0 + dcol;
                    float2 bb = *(const float2*)&bias[n];
                    float v0 = c[mi][ni][2 * p2] + bb.x;
                    float v1 = c[mi][ni][2 * p2 + 1] + bb.y;
                    if (is_qkv) {
                        float2 o; o.x = v0; o.y = v1;
                        *(float2*)&qkvdst[(size_t)m * HDIM + dcol] = o;
                    } else {
                        split_store2(g_a2h, g_a2l, (size_t)m * DM + (n - 6144),
                                     gelu_tanh(v0), gelu_tanh(v1));
                    }
                }
    } else {
        #pragma unroll
        for (int mi = 0; mi < 2; mi++)
            #pragma unroll
            for (int ni = 0; ni < 8; ni++)
                #pragma unroll
                for (int p2 = 0; p2 < 2; p2++) {
                    int m = m0 + wm * 32 + mi * 16 + g + p2 * 8;
                    int n = n0 + wn * 64 + ni * 8 + 2 * t4;
                    float2 bb = *(const float2*)&bias[n];
                    float v0 = c[mi][ni][2 * p2] + bb.x;
                    float v1 = c[mi][ni][2 * p2 + 1] + bb.y;
                    float2 xx = *(const float2*)&x[(size_t)m * DMODEL + n];
                    float2 gg = *(const float2*)&g_mod[2 * DMODEL + n];
                    float2 o;
                    o.x = xx.x + gg.x * v0;
                    o.y = xx.y + gg.y * v1;
                    *(float2*)&out[(size_t)m * DMODEL + n] = o;
                }
    }
}

// ---------------- K3: rms_norm + rope, q and k in one block ----------------
__global__ void k_rmsrope(const float* __restrict__ pe,
                          const float* __restrict__ q_scale,
                          const float* __restrict__ k_scale) {
    int t = blockIdx.x, h = blockIdx.y;
    int tid = threadIdx.x;
    int half = tid >> 7;        // 0 = q, 1 = k
    int d = tid & 127;
    float* buf = (half == 0 ? g_q : g_k) + ((size_t)h * LQ + t) * HDIM;
    const float* sc = (half == 0) ? q_scale : k_scale;
    __shared__ float spe[256];
    __shared__ float red[2][4];
    __shared__ float sv[2][HDIM];
    spe[tid] = pe[(size_t)t * 256 + tid];
    float v = buf[d];
    float ss = v * v;
    #pragma unroll
    for (int o = 16; o > 0; o >>= 1) ss += __shfl_xor_sync(0xffffffffu, ss, o);
    if ((d & 31) == 0) red[half][(d >> 5)] = ss;
    __syncthreads();
    float tot = red[half][0] + red[half][1] + red[half][2] + red[half][3];
    float n = rsqrtf(tot * (1.0f / HDIM) + 1e-6f);
    sv[half][d] = v * n * sc[d];
    __syncthreads();
    int j = d >> 1, r = d & 1;
    buf[d] = spe[j * 4 + r * 2] * sv[half][2 * j] +
             spe[j * 4 + r * 2 + 1] * sv[half][2 * j + 1];
}

// ---------------- K4: flash attention with packed f32x2 FMAs ----------------
#define QP 134
#define VP 66
#define PP 68
#define ATTN_SMEM_FLOATS (64 * QP + 64 * QP + 128 * VP + 64 * PP)
__global__ __launch_bounds__(256, 1) void k_attn() {
    extern __shared__ __align__(16) float smf[];
    float* sQ = smf;
    float* sK = sQ + 64 * QP;
    float* sV = sK + 64 * QP;
    float* sP = sV + 128 * VP;
    int head = blockIdx.y;
    int qt0 = blockIdx.x * 64;
    int tid = threadIdx.x;
    const float* Qg = g_q + (size_t)head * LQ * HDIM;
    const float* Kg = g_k + (size_t)head * LQ * HDIM;
    const float* Vg = g_v + (size_t)head * LQ * HDIM;

    {
        int c = tid >> 2, d0 = (tid & 3) * 32;
        const float* src = Qg + (size_t)(qt0 + c) * HDIM + d0;
        #pragma unroll
        for (int u = 0; u < 8; ++u) {
            float4 v = *(const float4*)(src + 4 * u);
            *(float2*)&sQ[c * QP + d0 + 4 * u] = make_float2(v.x, v.y);
            *(float2*)&sQ[c * QP + d0 + 4 * u + 2] = make_float2(v.z, v.w);
        }
    }

    int rq = (tid >> 4) * 4;
    int cl = tid & 15;

    float m_i[4], l_i[4];
    unsigned long long o2[4][8];
    #pragma unroll
    for (int i = 0; i < 4; i++) {
        m_i[i] = -INFINITY; l_i[i] = 0.f;
        #pragma unroll
        for (int u = 0; u < 8; u++) o2[i][u] = 0ull;
    }
    const float scale = 0.08838834764831845f;

    for (int kt0 = 0; kt0 < LQ; kt0 += 64) {
        __syncthreads();
        {
            int c = tid >> 2, d0 = (tid & 3) * 32;
            const float* srck = Kg + (size_t)(kt0 + c) * HDIM + d0;
            const float* srcv = Vg + (size_t)(kt0 + c) * HDIM + d0;
            #pragma unroll
            for (int u = 0; u < 8; ++u) {
                float4 kv = *(const float4*)(srck + 4 * u);
                *(float2*)&sK[c * QP + d0 + 4 * u] = make_float2(kv.x, kv.y);
                *(float2*)&sK[c * QP + d0 + 4 * u + 2] = make_float2(kv.z, kv.w);
                float4 vv = *(const float4*)(srcv + 4 * u);
                sV[(d0 + 4 * u + 0) * VP + c] = vv.x;
                sV[(d0 + 4 * u + 1) * VP + c] = vv.y;
                sV[(d0 + 4 * u + 2) * VP + c] = vv.z;
                sV[(d0 + 4 * u + 3) * VP + c] = vv.w;
            }
        }
        __syncthreads();

        unsigned long long s2[4][4];
        #pragma unroll
        for (int i = 0; i < 4; i++)
            #pragma unroll
            for (int u = 0; u < 4; u++) s2[i][u] = 0ull;
        #pragma unroll 8
        for (int k2 = 0; k2 < 64; k2++) {
            unsigned long long a0 = *(const unsigned long long*)&sQ[(rq + 0) * QP + 2 * k2];
            unsigned long long a1 = *(const unsigned long long*)&sQ[(rq + 1) * QP + 2 * k2];
            unsigned long long a2 = *(const unsigned long long*)&sQ[(rq + 2) * QP + 2 * k2];
            unsigned long long a3 = *(const unsigned long long*)&sQ[(rq + 3) * QP + 2 * k2];
            #pragma unroll
            for (int u = 0; u < 4; u++) {
                unsigned long long b =
                    *(const unsigned long long*)&sK[(cl + 16 * u) * QP + 2 * k2];
                FMA2(s2[0][u], a0, b);
                FMA2(s2[1][u], a1, b);
                FMA2(s2[2][u], a2, b);
                FMA2(s2[3][u], a3, b);
            }
        }

        #pragma unroll
        for (int i = 0; i < 4; i++) {
            float s0 = pairsum(s2[i][0]) * scale;
            float s1 = pairsum(s2[i][1]) * scale;
            float s2v = pairsum(s2[i][2]) * scale;
            float s3 = pairsum(s2[i][3]) * scale;
            float tm = fmaxf(fmaxf(s0, s1), fmaxf(s2v, s3));
            #pragma unroll
            for (int off = 8; off > 0; off >>= 1)
                tm = fmaxf(tm, __shfl_xor_sync(0xffffffffu, tm, off));
            float newm = fmaxf(m_i[i], tm);
            float corr = __expf(m_i[i] - newm);
            float p0 = __expf(s0 - newm), p1 = __expf(s1 - newm);
            float p2 = __expf(s2v - newm), p3 = __expf(s3 - newm);
            float ls = p0 + p1 + p2 + p3;
            #pragma unroll
            for (int off = 8; off > 0; off >>= 1)
                ls += __shfl_xor_sync(0xffffffffu, ls, off);
            l_i[i] = l_i[i] * corr + ls;
            m_i[i] = newm;
            unsigned long long corr2 = pack2(corr, corr);
            #pragma unroll
            for (int u = 0; u < 8; u++) MUL2(o2[i][u], corr2);
            sP[(rq + i) * PP + cl + 0]  = p0;
            sP[(rq + i) * PP + cl + 16] = p1;
            sP[(rq + i) * PP + cl + 32] = p2;
            sP[(rq + i) * PP + cl + 48] = p3;
        }
        __syncthreads();

        #pragma unroll 4
        for (int c2 = 0; c2 < 32; c2++) {
            unsigned long long a0 = *(const unsigned long long*)&sP[(rq + 0) * PP + 2 * c2];
            unsigned long long a1 = *(const unsigned long long*)&sP[(rq + 1) * PP + 2 * c2];
            unsigned long long a2 = *(const unsigned long long*)&sP[(rq + 2) * PP + 2 * c2];
            unsigned long long a3 = *(const unsigned long long*)&sP[(rq + 3) * PP + 2 * c2];
            #pragma unroll
            for (int u = 0; u < 8; u++) {
                unsigned long long b =
                    *(const unsigned long long*)&sV[(cl + 16 * u) * VP + 2 * c2];
                FMA2(o2[0][u], a0, b);
                FMA2(o2[1][u], a1, b);
                FMA2(o2[2][u], a2, b);
                FMA2(o2[3][u], a3, b);
            }
        }
    }

    #pragma unroll
    for (int i = 0; i < 4; i++) {
        float inv = 1.f / l_i[i];
        int t = qt0 + rq + i;
        size_t rowb = (size_t)t * DM + head * HDIM;
        #pragma unroll
        for (int u = 0; u < 8; u++) {
            float val = pairsum(o2[i][u]) * inv;
            split_store(g_a2h, g_a2l, rowb + cl + 16 * u, val);
        }
    }
}

// ---------------- launch ----------------
extern "C" void kernel_launch(void* const* d_in, const int* in_sizes, int n_in,
                              void* d_out, int out_size) {
    (void)in_sizes; (void)n_in; (void)out_size;
    const float* x       = (const float*)d_in[1];
    const float* vec     = (const float*)d_in[2];
    const float* pe      = (const float*)d_in[3];
    const float* mod_w   = (const float*)d_in[4];
    const float* mod_b   = (const float*)d_in[5];
    const float* w1      = (const float*)d_in[6];
    const float* b1      = (const float*)d_in[7];
    const float* w2      = (const float*)d_in[8];
    const float* b2      = (const float*)d_in[9];
    const float* q_scale = (const float*)d_in[10];
    const float* k_scale = (const float*)d_in[11];
    float* out = (float*)d_out;

    static int attr_done = 0;
    if (!attr_done) {
        cudaFuncSetAttribute(k_attn, cudaFuncAttributeMaxDynamicSharedMemorySize,
                             ATTN_SMEM_FLOATS * (int)sizeof(float));
        cudaFuncSetAttribute(k_gemm_bf<0>,
                             cudaFuncAttributeMaxDynamicSharedMemorySize, GEMM_SMEM);
        cudaFuncSetAttribute(k_gemm_bf<1>,
                             cudaFuncAttributeMaxDynamicSharedMemorySize, GEMM_SMEM);
        attr_done = 1;
    }
    static __nv_bfloat16 *a1h, *a1l, *b1h, *b1l, *a2h, *a2l, *b2h, *b2l;
    if (!a1h) {
        cudaGetSymbolAddress((void**)&a1h, g_a1h);
        cudaGetSymbolAddress((void**)&a1l, g_a1l);
        cudaGetSymbolAddress((void**)&b1h, g_b1h);
        cudaGetSymbolAddress((void**)&b1l, g_b1l);
        cudaGetSymbolAddress((void**)&a2h, g_a2h);
        cudaGetSymbolAddress((void**)&a2l, g_a2l);
        cudaGetSymbolAddress((void**)&b2h, g_b2h);
        cudaGetSymbolAddress((void**)&b2l, g_b2l);
    }

    k_zero<<<(3 * DMODEL) / 256, 256>>>();
    k_mod<<<dim3((3 * DMODEL) / 256, 8), 256>>>(vec, mod_w, mod_b);
    k_xmod<<<LQ, 256>>>(x);
    k_cvt_t<<<dim3(N1 / 64, DMODEL / 32), 256>>>(w1, b1h, b1l, DMODEL, N1);
    k_gemm_bf<0><<<dim3(LQ / 128, N1 / 128), 256, GEMM_SMEM>>>(
        a1h, a1l, b1h, b1l, DMODEL, b1, nullptr, nullptr);
    k_rmsrope<<<dim3(LQ, NHEAD), 256>>>(pe, q_scale, k_scale);
    k_attn<<<dim3(LQ / 64, NHEAD), 256, ATTN_SMEM_FLOATS * sizeof(float)>>>();
    k_cvt_t<<<dim3(DMODEL / 64, DM / 32), 256>>>(w2, b2h, b2l, DM, DMODEL);
    k_gemm_bf<1><<<dim3(LQ / 128, DMODEL / 128), 256, GEMM_SMEM>>>(
        a2h, a2l, b2h, b2l, DM, b2, x, out);
}

// round 17
// speedup vs baseline: 1.0172x; 1.0004x over previous
#include <cuda_runtime.h>
#include <cuda_bf16.h>
#include <math.h>
#include <stdint.h>

#define LQ 2048
#define DMODEL 3072
#define NHEAD 24
#define HDIM 128
#define MLPD 12288
#define N1 21504   // 3*D + MLP
#define DM 15360   // D + MLP
#define TD3 9216   // 3*D

// ---------------- scratch (device globals; no allocation allowed) ----------------
__device__ float g_mod[3 * DMODEL];          // [shift | scale | gate]
__device__ float g_q[(size_t)NHEAD * LQ * HDIM];
__device__ float g_k[(size_t)NHEAD * LQ * HDIM];
__device__ float g_v[(size_t)NHEAD * LQ * HDIM];

// split-bf16 operands (hi/lo): A matrices [M][K], B matrices [N][K]
__device__ __align__(128) __nv_bfloat16 g_a1h[(size_t)LQ * DMODEL];
__device__ __align__(128) __nv_bfloat16 g_a1l[(size_t)LQ * DMODEL];
__device__ __align__(128) __nv_bfloat16 g_b1h[(size_t)N1 * DMODEL];
__device__ __align__(128) __nv_bfloat16 g_b1l[(size_t)N1 * DMODEL];
__device__ __align__(128) __nv_bfloat16 g_a2h[(size_t)LQ * DM];
__device__ __align__(128) __nv_bfloat16 g_a2l[(size_t)LQ * DM];
__device__ __align__(128) __nv_bfloat16 g_b2h[(size_t)DMODEL * DM];
__device__ __align__(128) __nv_bfloat16 g_b2l[(size_t)DMODEL * DM];

// ---------------- PTX helpers ----------------
#define CP16(saddr, gptr) \
    asm volatile("cp.async.cg.shared.global [%0], [%1], 16;\n" \
                 :: "r"(saddr), "l"(gptr))
#define CP_COMMIT() asm volatile("cp.async.commit_group;\n")
#define CP_WAIT(n)  asm volatile("cp.async.wait_group %0;\n" :: "n"(n))

__device__ __forceinline__ void mma_bf16(float* c, const uint32_t* a,
                                         uint32_t b0, uint32_t b1) {
    asm volatile(
        "mma.sync.aligned.m16n8k16.row.col.f32.bf16.bf16.f32 "
        "{%0,%1,%2,%3}, {%4,%5,%6,%7}, {%8,%9}, {%0,%1,%2,%3};"
        : "+f"(c[0]), "+f"(c[1]), "+f"(c[2]), "+f"(c[3])
        : "r"(a[0]), "r"(a[1]), "r"(a[2]), "r"(a[3]), "r"(b0), "r"(b1));
}

// packed fp32x2 (FFMA2)
#define FMA2(c, a, b) \
    asm("fma.rn.f32x2 %0, %1, %2, %0;" : "+l"(c) : "l"(a), "l"(b))
#define MUL2(c, a) \
    asm("mul.rn.f32x2 %0, %0, %1;" : "+l"(c) : "l"(a))

__device__ __forceinline__ unsigned long long pack2(float lo, float hi) {
    unsigned long long r;
    asm("mov.b64 %0, {%1,%2};" : "=l"(r)
        : "r"(__float_as_uint(lo)), "r"(__float_as_uint(hi)));
    return r;
}
__device__ __forceinline__ float pairsum(unsigned long long v) {
    return __uint_as_float((unsigned)v) + __uint_as_float((unsigned)(v >> 32));
}

__device__ __forceinline__ void split_store(__nv_bfloat16* dh, __nv_bfloat16* dl,
                                            size_t idx, float v) {
    __nv_bfloat16 h = __float2bfloat16(v);
    dh[idx] = h;
    dl[idx] = __float2bfloat16(v - __bfloat162float(h));
}

__device__ __forceinline__ void split_store2(__nv_bfloat16* dh, __nv_bfloat16* dl,
                                             size_t idx, float v0, float v1) {
    __nv_bfloat16 h0 = __float2bfloat16(v0);
    __nv_bfloat16 h1 = __float2bfloat16(v1);
    __nv_bfloat162 hh; hh.x = h0; hh.y = h1;
    *(__nv_bfloat162*)&dh[idx] = hh;
    __nv_bfloat162 ll;
    ll.x = __float2bfloat16(v0 - __bfloat162float(h0));
    ll.y = __float2bfloat16(v1 - __bfloat162float(h1));
    *(__nv_bfloat162*)&dl[idx] = ll;
}

// HW tanh (MUFU.TANH)
__device__ __forceinline__ float gelu_tanh(float v) {
    float arg = 0.7978845608028654f * (v + 0.044715f * v * v * v);
    float t;
    asm("tanh.approx.f32 %0, %1;" : "=f"(t) : "f"(arg));
    return 0.5f * v * (1.f + t);
}

// ---------------- K0: mod = silu(vec) @ mod_w + mod_b (split-K + atomics) ----
__global__ void k_zero() { g_mod[blockIdx.x * 256 + threadIdx.x] = 0.f; }

__global__ void k_mod(const float* __restrict__ vec,
                      const float* __restrict__ mod_w,
                      const float* __restrict__ mod_b) {
    __shared__ float sv[384];
    int k0 = blockIdx.y * 384;
    for (int i = threadIdx.x; i < 384; i += 256) {
        float v = vec[k0 + i];
        sv[i] = v / (1.0f + expf(-v));
    }
    __syncthreads();
    int col = blockIdx.x * 256 + threadIdx.x;
    float acc = (blockIdx.y == 0) ? mod_b[col] : 0.f;
    for (int i = 0; i < 384; ++i)
        acc = fmaf(sv[i], mod_w[(size_t)(k0 + i) * (3 * DMODEL) + col], acc);
    atomicAdd(&g_mod[col], acc);
}

__device__ __forceinline__ float block_sum_256(float v, float* red8) {
    #pragma unroll
    for (int o = 16; o > 0; o >>= 1) v += __shfl_xor_sync(0xffffffffu, v, o);
    if ((threadIdx.x & 31) == 0) red8[threadIdx.x >> 5] = v;
    __syncthreads();
    float t = 0.f;
    #pragma unroll
    for (int i = 0; i < 8; ++i) t += red8[i];
    __syncthreads();
    return t;
}

// ---------------- K1: x_mod -> bf16 hi/lo (one-pass stats) ----------------
__global__ void k_xmod(const float* __restrict__ x) {
    __shared__ float red8[8];
    int t = blockIdx.x;
    const float* xr = x + (size_t)t * DMODEL;
    float s = 0.f, sq = 0.f;
    for (int i = threadIdx.x * 4; i < DMODEL; i += 1024) {
        float4 v = *(const float4*)&xr[i];
        s += (v.x + v.y) + (v.z + v.w);
        sq += v.x * v.x + v.y * v.y + v.z * v.z + v.w * v.w;
    }
    float mu = block_sum_256(s, red8) * (1.0f / DMODEL);
    float ex2 = block_sum_256(sq, red8) * (1.0f / DMODEL);
    float var = ex2 - mu * mu;
    float rstd = rsqrtf(var + 1e-6f);
    for (int i = threadIdx.x * 4; i < DMODEL; i += 1024) {
        float4 v = *(const float4*)&xr[i];
        float4 sh = *(const float4*)&g_mod[i];
        float4 sc = *(const float4*)&g_mod[DMODEL + i];
        float o0 = sh.x + (1.0f + sc.x) * ((v.x - mu) * rstd);
        float o1 = sh.y + (1.0f + sc.y) * ((v.y - mu) * rstd);
        float o2 = sh.z + (1.0f + sc.z) * ((v.z - mu) * rstd);
        float o3 = sh.w + (1.0f + sc.w) * ((v.w - mu) * rstd);
        size_t base = (size_t)t * DMODEL + i;
        split_store2(g_a1h, g_a1l, base, o0, o1);
        split_store2(g_a1h, g_a1l, base + 2, o2, o3);
    }
}

// ---------------- transpose + split (v5): quad 32x32 tiles, MLP=4 ----------
// src[R][C] fp32 -> dst[C][R] bf16 hi/lo. Four column-tiles per block; v2's
// proven conflict-free 32x33 pattern, all four global loads front-batched.
__global__ void k_cvt_t(const float* __restrict__ src,
                        __nv_bfloat16* __restrict__ dh,
                        __nv_bfloat16* __restrict__ dl, int R, int C) {
    __shared__ float tile[4][32][33];
    int c0 = blockIdx.x * 128, r0 = blockIdx.y * 32;
    int t = threadIdx.x;
    {
        int r = t >> 3, c4 = (t & 7) * 4;
        const float* s0 = &src[(size_t)(r0 + r) * C + c0 + c4];
        float4 v0 = *(const float4*)(s0);
        float4 v1 = *(const float4*)(s0 + 32);
        float4 v2 = *(const float4*)(s0 + 64);
        float4 v3 = *(const float4*)(s0 + 96);
        tile[0][r][c4 + 0] = v0.x; tile[0][r][c4 + 1] = v0.y;
        tile[0][r][c4 + 2] = v0.z; tile[0][r][c4 + 3] = v0.w;
        tile[1][r][c4 + 0] = v1.x; tile[1][r][c4 + 1] = v1.y;
        tile[1][r][c4 + 2] = v1.z; tile[1][r][c4 + 3] = v1.w;
        tile[2][r][c4 + 0] = v2.x; tile[2][r][c4 + 1] = v2.y;
        tile[2][r][c4 + 2] = v2.z; tile[2][r][c4 + 3] = v2.w;
        tile[3][r][c4 + 0] = v3.x; tile[3][r][c4 + 1] = v3.y;
        tile[3][r][c4 + 2] = v3.z; tile[3][r][c4 + 3] = v3.w;
    }
    __syncthreads();
    #pragma unroll
    for (int q = 0; q < 4; q++) {
        int c = t >> 3, r4 = (t & 7) * 4;
        float f0 = tile[q][r4 + 0][c];
        float f1 = tile[q][r4 + 1][c];
        float f2 = tile[q][r4 + 2][c];
        float f3 = tile[q][r4 + 3][c];
        __nv_bfloat16 h0 = __float2bfloat16(f0);
        __nv_bfloat16 h1 = __float2bfloat16(f1);
        __nv_bfloat16 h2 = __float2bfloat16(f2);
        __nv_bfloat16 h3 = __float2bfloat16(f3);
        size_t idx = (size_t)(c0 + q * 32 + c) * R + r0 + r4;
        uint2 hp;
        hp.x = ((uint32_t)*(uint16_t*)&h0) | (((uint32_t)*(uint16_t*)&h1) << 16);
        hp.y = ((uint32_t)*(uint16_t*)&h2) | (((uint32_t)*(uint16_t*)&h3) << 16);
        *(uint2*)&dh[idx] = hp;
        __nv_bfloat16 l0 = __float2bfloat16(f0 - __bfloat162float(h0));
        __nv_bfloat16 l1 = __float2bfloat16(f1 - __bfloat162float(h1));
        __nv_bfloat16 l2 = __float2bfloat16(f2 - __bfloat162float(h2));
        __nv_bfloat16 l3 = __float2bfloat16(f3 - __bfloat162float(h3));
        uint2 lp;
        lp.x = ((uint32_t)*(uint16_t*)&l0) | (((uint32_t)*(uint16_t*)&l1) << 16);
        lp.y = ((uint32_t)*(uint16_t*)&l2) | (((uint32_t)*(uint16_t*)&l3) << 16);
        *(uint2*)&dl[idx] = lp;
    }
}

// ---------------- split-bf16 HMMA GEMM (round-4 proven mainloop) ----------------
#define ROWW 40
#define SLAB_W 2560
#define STAGE_B 40960
#define GEMM_SMEM (2 * STAGE_B)

__device__ __forceinline__ void ld_stage_b(
    const __nv_bfloat16* Ah, const __nv_bfloat16* Al,
    const __nv_bfloat16* Bh, const __nv_bfloat16* Bl,
    int K, int m0, int n0, int k0, uint32_t sm, int tid) {
    int row = tid >> 1;
    int cb = (tid & 1) * 32;
    uint32_t so = row * (ROWW * 2) + cb;
    const char* ga = (const char*)(Ah + (size_t)(m0 + row) * K + k0) + cb;
    CP16(sm + so, ga); CP16(sm + so + 16, ga + 16);
    const char* gal = (const char*)(Al + (size_t)(m0 + row) * K + k0) + cb;
    CP16(sm + 10240 + so, gal); CP16(sm + 10240 + so + 16, gal + 16);
    const char* gb = (const char*)(Bh + (size_t)(n0 + row) * K + k0) + cb;
    CP16(sm + 20480 + so, gb); CP16(sm + 20480 + so + 16, gb + 16);
    const char* gbl = (const char*)(Bl + (size_t)(n0 + row) * K + k0) + cb;
    CP16(sm + 30720 + so, gbl); CP16(sm + 30720 + so + 16, gbl + 16);
}

template <int EPI>
__global__ __launch_bounds__(256, 2) void k_gemm_bf(
    const __nv_bfloat16* __restrict__ Ah, const __nv_bfloat16* __restrict__ Al,
    const __nv_bfloat16* __restrict__ Bh, const __nv_bfloat16* __restrict__ Bl,
    int K, const float* __restrict__ bias,
    const float* __restrict__ x, float* __restrict__ out) {
    extern __shared__ __align__(16) char smc[];
    uint32_t sbase;
    asm("{ .reg .u64 t; cvta.to.shared.u64 t, %1; cvt.u32.u64 %0, t; }"
        : "=r"(sbase) : "l"(smc));

    int tid = threadIdx.x;
    int m0 = blockIdx.x * 128;
    int n0 = blockIdx.y * 128;
    int lane = tid & 31, w = tid >> 5;
    int g = lane >> 2, t4 = lane & 3;
    int wm = w & 3, wn = w >> 2;

    float c[2][8][4];
    #pragma unroll
    for (int mi = 0; mi < 2; mi++)
        #pragma unroll
        for (int ni = 0; ni < 8; ni++)
            #pragma unroll
            for (int cc = 0; cc < 4; cc++) c[mi][ni][cc] = 0.f;

    int nst = K / 32;
    ld_stage_b(Ah, Al, Bh, Bl, K, m0, n0, 0, sbase, tid);
    CP_COMMIT();

    for (int kt = 0; kt < nst; ++kt) {
        if (kt + 1 < nst) {
            ld_stage_b(Ah, Al, Bh, Bl, K, m0, n0, (kt + 1) * 32,
                       sbase + ((kt + 1) & 1) * STAGE_B, tid);
            CP_COMMIT();
            CP_WAIT(1);
        } else {
            CP_WAIT(0);
        }
        __syncthreads();

        const uint32_t* st = (const uint32_t*)(smc + (kt & 1) * STAGE_B);
        const uint32_t* sal = st + SLAB_W;
        const uint32_t* sbh = st + 2 * SLAB_W;
        const uint32_t* sbl = st + 3 * SLAB_W;

        #pragma unroll
        for (int ks = 0; ks < 2; ks++) {
            int kw = ks * 8;
            uint32_t ah[2][4], al[2][4];
            #pragma unroll
            for (int mi = 0; mi < 2; mi++) {
                int r = wm * 32 + mi * 16;
                int bi = (r + g) * 20 + t4 + kw;
                ah[mi][0] = st[bi];        ah[mi][1] = st[bi + 160];
                ah[mi][2] = st[bi + 4];    ah[mi][3] = st[bi + 164];
                al[mi][0] = sal[bi];       al[mi][1] = sal[bi + 160];
                al[mi][2] = sal[bi + 4];   al[mi][3] = sal[bi + 164];
            }
            #pragma unroll
            for (int p = 0; p < 4; p++) {
                int n = wn * 64 + p * 16;
                int bj = (n + g) * 20 + t4 + kw;
                uint32_t bh0 = sbh[bj], bh1 = sbh[bj + 4];
                uint32_t bl0 = sbl[bj], bl1 = sbl[bj + 4];
                mma_bf16(c[0][2 * p], ah[0], bh0, bh1);
                mma_bf16(c[1][2 * p], ah[1], bh0, bh1);
                mma_bf16(c[0][2 * p], al[0], bh0, bh1);
                mma_bf16(c[1][2 * p], al[1], bh0, bh1);
                mma_bf16(c[0][2 * p], ah[0], bl0, bl1);
                mma_bf16(c[1][2 * p], ah[1], bl0, bl1);
                int bj2 = (n + 8 + g) * 20 + t4 + kw;
                uint32_t ch0 = sbh[bj2], ch1 = sbh[bj2 + 4];
                uint32_t cl0 = sbl[bj2], cl1 = sbl[bj2 + 4];
                mma_bf16(c[0][2 * p + 1], ah[0], ch0, ch1);
                mma_bf16(c[1][2 * p + 1], ah[1], ch0, ch1);
                mma_bf16(c[0][2 * p + 1], al[0], ch0, ch1);
                mma_bf16(c[1][2 * p + 1], al[1], ch0, ch1);
                mma_bf16(c[0][2 * p + 1], ah[0], cl0, cl1);
                mma_bf16(c[1][2 * p + 1], ah[1], cl0, cl1);
            }
        }
        __syncthreads();
    }

    // ---- epilogue: paired stores (cc pairs are adjacent n, same m) ----
    if (EPI == 0) {
        bool is_qkv = n0 < TD3;
        float* qkvdst = nullptr;
        if (is_qkv) {
            int which = n0 / DMODEL;
            int head = (n0 % DMODEL) / HDIM;
            float* base = (which == 0) ? g_q : (which == 1) ? g_k : g_v;
            qkvdst = base + (size_t)head * LQ * HDIM;
        }
        #pragma unroll
        for (int mi = 0; mi < 2; mi++)
            #pragma unroll
            for (int ni = 0; ni < 8; ni++)
                #pragma unroll
                for (int p2 = 0; p2 < 2; p2++) {
                    int m = m0 + wm * 32 + mi * 16 + g + p2 * 8;
                    int dcol = wn * 64 + ni * 8 + 2 * t4;
                    int n = n0 + dcol;
                    float2 bb = *(const float2*)&bias[n];
                    float v0 = c[mi][ni][2 * p2] + bb.x;
                    float v1 = c[mi][ni][2 * p2 + 1] + bb.y;
                    if (is_qkv) {
                        float2 o; o.x = v0; o.y = v1;
                        *(float2*)&qkvdst[(size_t)m * HDIM + dcol] = o;
                    } else {
                        split_store2(g_a2h, g_a2l, (size_t)m * DM + (n - 6144),
                                     gelu_tanh(v0), gelu_tanh(v1));
                    }
                }
    } else {
        #pragma unroll
        for (int mi = 0; mi < 2; mi++)
            #pragma unroll
            for (int ni = 0; ni < 8; ni++)
                #pragma unroll
                for (int p2 = 0; p2 < 2; p2++) {
                    int m = m0 + wm * 32 + mi * 16 + g + p2 * 8;
                    int n = n0 + wn * 64 + ni * 8 + 2 * t4;
                    float2 bb = *(const float2*)&bias[n];
                    float v0 = c[mi][ni][2 * p2] + bb.x;
                    float v1 = c[mi][ni][2 * p2 + 1] + bb.y;
                    float2 xx = *(const float2*)&x[(size_t)m * DMODEL + n];
                    float2 gg = *(const float2*)&g_mod[2 * DMODEL + n];
                    float2 o;
                    o.x = xx.x + gg.x * v0;
                    o.y = xx.y + gg.y * v1;
                    *(float2*)&out[(size_t)m * DMODEL + n] = o;
                }
    }
}

// ---------------- K3: rms_norm + rope, q and k in one block ----------------
__global__ void k_rmsrope(const float* __restrict__ pe,
                          const float* __restrict__ q_scale,
                          const float* __restrict__ k_scale) {
    int t = blockIdx.x, h = blockIdx.y;
    int tid = threadIdx.x;
    int half = tid >> 7;        // 0 = q, 1 = k
    int d = tid & 127;
    float* buf = (half == 0 ? g_q : g_k) + ((size_t)h * LQ + t) * HDIM;
    const float* sc = (half == 0) ? q_scale : k_scale;
    __shared__ float spe[256];
    __shared__ float red[2][4];
    __shared__ float sv[2][HDIM];
    spe[tid] = pe[(size_t)t * 256 + tid];
    float v = buf[d];
    float ss = v * v;
    #pragma unroll
    for (int o = 16; o > 0; o >>= 1) ss += __shfl_xor_sync(0xffffffffu, ss, o);
    if ((d & 31) == 0) red[half][(d >> 5)] = ss;
    __syncthreads();
    float tot = red[half][0] + red[half][1] + red[half][2] + red[half][3];
    float n = rsqrtf(tot * (1.0f / HDIM) + 1e-6f);
    sv[half][d] = v * n * sc[d];
    __syncthreads();
    int j = d >> 1, r = d & 1;
    buf[d] = spe[j * 4 + r * 2] * sv[half][2 * j] +
             spe[j * 4 + r * 2 + 1] * sv[half][2 * j + 1];
}

// ---------------- K4: flash attention with packed f32x2 FMAs ----------------
#define QP 134
#define VP 66
#define PP 68
#define ATTN_SMEM_FLOATS (64 * QP + 64 * QP + 128 * VP + 64 * PP)
__global__ __launch_bounds__(256, 1) void k_attn() {
    extern __shared__ __align__(16) float smf[];
    float* sQ = smf;
    float* sK = sQ + 64 * QP;
    float* sV = sK + 64 * QP;
    float* sP = sV + 128 * VP;
    int head = blockIdx.y;
    int qt0 = blockIdx.x * 64;
    int tid = threadIdx.x;
    const float* Qg = g_q + (size_t)head * LQ * HDIM;
    const float* Kg = g_k + (size_t)head * LQ * HDIM;
    const float* Vg = g_v + (size_t)head * LQ * HDIM;

    {
        int c = tid >> 2, d0 = (tid & 3) * 32;
        const float* src = Qg + (size_t)(qt0 + c) * HDIM + d0;
        #pragma unroll
        for (int u = 0; u < 8; ++u) {
            float4 v = *(const float4*)(src + 4 * u);
            *(float2*)&sQ[c * QP + d0 + 4 * u] = make_float2(v.x, v.y);
            *(float2*)&sQ[c * QP + d0 + 4 * u + 2] = make_float2(v.z, v.w);
        }
    }

    int rq = (tid >> 4) * 4;
    int cl = tid & 15;

    float m_i[4], l_i[4];
    unsigned long long o2[4][8];
    #pragma unroll
    for (int i = 0; i < 4; i++) {
        m_i[i] = -INFINITY; l_i[i] = 0.f;
        #pragma unroll
        for (int u = 0; u < 8; u++) o2[i][u] = 0ull;
    }
    const float scale = 0.08838834764831845f;

    for (int kt0 = 0; kt0 < LQ; kt0 += 64) {
        __syncthreads();
        {
            int c = tid >> 2, d0 = (tid & 3) * 32;
            const float* srck = Kg + (size_t)(kt0 + c) * HDIM + d0;
            const float* srcv = Vg + (size_t)(kt0 + c) * HDIM + d0;
            #pragma unroll
            for (int u = 0; u < 8; ++u) {
                float4 kv = *(const float4*)(srck + 4 * u);
                *(float2*)&sK[c * QP + d0 + 4 * u] = make_float2(kv.x, kv.y);
                *(float2*)&sK[c * QP + d0 + 4 * u + 2] = make_float2(kv.z, kv.w);
                float4 vv = *(const float4*)(srcv + 4 * u);
                sV[(d0 + 4 * u + 0) * VP + c] = vv.x;
                sV[(d0 + 4 * u + 1) * VP + c] = vv.y;
                sV[(d0 + 4 * u + 2) * VP + c] = vv.z;
                sV[(d0 + 4 * u + 3) * VP + c] = vv.w;
            }
        }
        __syncthreads();

        unsigned long long s2[4][4];
        #pragma unroll
        for (int i = 0; i < 4; i++)
            #pragma unroll
            for (int u = 0; u < 4; u++) s2[i][u] = 0ull;
        #pragma unroll 8
        for (int k2 = 0; k2 < 64; k2++) {
            unsigned long long a0 = *(const unsigned long long*)&sQ[(rq + 0) * QP + 2 * k2];
            unsigned long long a1 = *(const unsigned long long*)&sQ[(rq + 1) * QP + 2 * k2];
            unsigned long long a2 = *(const unsigned long long*)&sQ[(rq + 2) * QP + 2 * k2];
            unsigned long long a3 = *(const unsigned long long*)&sQ[(rq + 3) * QP + 2 * k2];
            #pragma unroll
            for (int u = 0; u < 4; u++) {
                unsigned long long b =
                    *(const unsigned long long*)&sK[(cl + 16 * u) * QP + 2 * k2];
                FMA2(s2[0][u], a0, b);
                FMA2(s2[1][u], a1, b);
                FMA2(s2[2][u], a2, b);
                FMA2(s2[3][u], a3, b);
            }
        }

        #pragma unroll
        for (int i = 0; i < 4; i++) {
            float s0 = pairsum(s2[i][0]) * scale;
            float s1 = pairsum(s2[i][1]) * scale;
            float s2v = pairsum(s2[i][2]) * scale;
            float s3 = pairsum(s2[i][3]) * scale;
            float tm = fmaxf(fmaxf(s0, s1), fmaxf(s2v, s3));
            #pragma unroll
            for (int off = 8; off > 0; off >>= 1)
                tm = fmaxf(tm, __shfl_xor_sync(0xffffffffu, tm, off));
            float newm = fmaxf(m_i[i], tm);
            float corr = __expf(m_i[i] - newm);
            float p0 = __expf(s0 - newm), p1 = __expf(s1 - newm);
            float p2 = __expf(s2v - newm), p3 = __expf(s3 - newm);
            float ls = p0 + p1 + p2 + p3;
            #pragma unroll
            for (int off = 8; off > 0; off >>= 1)
                ls += __shfl_xor_sync(0xffffffffu, ls, off);
            l_i[i] = l_i[i] * corr + ls;
            m_i[i] = newm;
            unsigned long long corr2 = pack2(corr, corr);
            #pragma unroll
            for (int u = 0; u < 8; u++) MUL2(o2[i][u], corr2);
            sP[(rq + i) * PP + cl + 0]  = p0;
            sP[(rq + i) * PP + cl + 16] = p1;
            sP[(rq + i) * PP + cl + 32] = p2;
            sP[(rq + i) * PP + cl + 48] = p3;
        }
        __syncthreads();

        #pragma unroll 4
        for (int c2 = 0; c2 < 32; c2++) {
            unsigned long long a0 = *(const unsigned long long*)&sP[(rq + 0) * PP + 2 * c2];
            unsigned long long a1 = *(const unsigned long long*)&sP[(rq + 1) * PP + 2 * c2];
            unsigned long long a2 = *(const unsigned long long*)&sP[(rq + 2) * PP + 2 * c2];
            unsigned long long a3 = *(const unsigned long long*)&sP[(rq + 3) * PP + 2 * c2];
            #pragma unroll
            for (int u = 0; u < 8; u++) {
                unsigned long long b =
                    *(const unsigned long long*)&sV[(cl + 16 * u) * VP + 2 * c2];
                FMA2(o2[0][u], a0, b);
                FMA2(o2[1][u], a1, b);
                FMA2(o2[2][u], a2, b);
                FMA2(o2[3][u], a3, b);
            }
        }
    }

    #pragma unroll
    for (int i = 0; i < 4; i++) {
        float inv = 1.f / l_i[i];
        int t = qt0 + rq + i;
        size_t rowb = (size_t)t * DM + head * HDIM;
        #pragma unroll
        for (int u = 0; u < 8; u++) {
            float val = pairsum(o2[i][u]) * inv;
            split_store(g_a2h, g_a2l, rowb + cl + 16 * u, val);
        }
    }
}

// ---------------- launch ----------------
extern "C" void kernel_launch(void* const* d_in, const int* in_sizes, int n_in,
                              void* d_out, int out_size) {
    (void)in_sizes; (void)n_in; (void)out_size;
    const float* x       = (const float*)d_in[1];
    const float* vec     = (const float*)d_in[2];
    const float* pe      = (const float*)d_in[3];
    const float* mod_w   = (const float*)d_in[4];
    const float* mod_b   = (const float*)d_in[5];
    const float* w1      = (const float*)d_in[6];
    const float* b1      = (const float*)d_in[7];
    const float* w2      = (const float*)d_in[8];
    const float* b2      = (const float*)d_in[9];
    const float* q_scale = (const float*)d_in[10];
    const float* k_scale = (const float*)d_in[11];
    float* out = (float*)d_out;

    static int attr_done = 0;
    if (!attr_done) {
        cudaFuncSetAttribute(k_attn, cudaFuncAttributeMaxDynamicSharedMemorySize,
                             ATTN_SMEM_FLOATS * (int)sizeof(float));
        cudaFuncSetAttribute(k_gemm_bf<0>,
                             cudaFuncAttributeMaxDynamicSharedMemorySize, GEMM_SMEM);
        cudaFuncSetAttribute(k_gemm_bf<1>,
                             cudaFuncAttributeMaxDynamicSharedMemorySize, GEMM_SMEM);
        attr_done = 1;
    }
    static __nv_bfloat16 *a1h, *a1l, *b1h, *b1l, *a2h, *a2l, *b2h, *b2l;
    if (!a1h) {
        cudaGetSymbolAddress((void**)&a1h, g_a1h);
        cudaGetSymbolAddress((void**)&a1l, g_a1l);
        cudaGetSymbolAddress((void**)&b1h, g_b1h);
        cudaGetSymbolAddress((void**)&b1l, g_b1l);
        cudaGetSymbolAddress((void**)&a2h, g_a2h);
        cudaGetSymbolAddress((void**)&a2l, g_a2l);
        cudaGetSymbolAddress((void**)&b2h, g_b2h);
        cudaGetSymbolAddress((void**)&b2l, g_b2l);
    }

    k_zero<<<(3 * DMODEL) / 256, 256>>>();
    k_mod<<<dim3((3 * DMODEL) / 256, 8), 256>>>(vec, mod_w, mod_b);
    k_xmod<<<LQ, 256>>>(x);
    k_cvt_t<<<dim3(N1 / 128, DMODEL / 32), 256>>>(w1, b1h, b1l, DMODEL, N1);
    k_gemm_bf<0><<<dim3(LQ / 128, N1 / 128), 256, GEMM_SMEM>>>(
        a1h, a1l, b1h, b1l, DMODEL, b1, nullptr, nullptr);
    k_rmsrope<<<dim3(LQ, NHEAD), 256>>>(pe, q_scale, k_scale);
    k_attn<<<dim3(LQ / 64, NHEAD), 256, ATTN_SMEM_FLOATS * sizeof(float)>>>();
    k_cvt_t<<<dim3(DMODEL / 128, DM / 32), 256>>>(w2, b2h, b2l, DM, DMODEL);
    k_gemm_bf<1><<<dim3(LQ / 128, DMODEL / 128), 256, GEMM_SMEM>>>(
        a2h, a2l, b2h, b2l, DM, b2, x, out);
}